// round 2
// baseline (speedup 1.0000x reference)
#include <cuda_runtime.h>
#include <math_constants.h>
#include <cstdint>

// Shapes (fixed):
//   word_features  [B, D, T]   = [32, 256, 32]   fp32   d_in[0]
//   image_features [B, Dh,H,W] = [32, 128,128,128] fp32 d_in[1]
//   words_mask     [B, T]      = [32, 32]        int32  d_in[2]
//   W              [Dh, D]     = [128, 256]      fp32   d_in[3]
//   b              [Dh]        = [128]           fp32   d_in[4]
// Outputs: attn [B,Dh,N] at 0, attn_coefficients [B,N,T] at B*Dh*N.

#define B_   32
#define D_   256
#define T_   32
#define DH_  128
#define N_   16384
#define ILP  4

__device__ float g_values[B_ * DH_ * T_];

// ---------------- packed f32x2 helpers ----------------
__device__ __forceinline__ unsigned long long pk2(float lo, float hi) {
    unsigned long long r;
    asm("mov.b64 %0, {%1, %2};" : "=l"(r) : "f"(lo), "f"(hi));
    return r;
}
__device__ __forceinline__ float2 unpk2(unsigned long long v) {
    float2 f;
    asm("mov.b64 {%0, %1}, %2;" : "=f"(f.x), "=f"(f.y) : "l"(v));
    return f;
}
__device__ __forceinline__ unsigned long long ffma2(unsigned long long a,
                                                    unsigned long long b,
                                                    unsigned long long c) {
    unsigned long long d;
    asm("fma.rn.f32x2 %0, %1, %2, %3;" : "=l"(d) : "l"(a), "l"(b), "l"(c));
    return d;
}

// ---------------- kernel 1: values = W * wf + b ----------------
__global__ void values_kernel(const float* __restrict__ wf,
                              const float* __restrict__ Wm,
                              const float* __restrict__ bias) {
    __shared__ float swf[D_ * T_];
    const int b = blockIdx.x;
    const int k = threadIdx.x;

    const float* wfb = wf + (size_t)b * D_ * T_;
    for (int i = threadIdx.x; i < D_ * T_; i += blockDim.x)
        swf[i] = wfb[i];
    __syncthreads();

    float acc[T_];
    const float bk = bias[k];
#pragma unroll
    for (int t = 0; t < T_; t++) acc[t] = bk;

    const float* wrow = Wm + (size_t)k * D_;
#pragma unroll 4
    for (int d = 0; d < D_; d++) {
        const float w = wrow[d];
        const float4* row4 = reinterpret_cast<const float4*>(&swf[d * T_]);
#pragma unroll
        for (int j = 0; j < T_ / 4; j++) {
            float4 v = row4[j];
            acc[4 * j + 0] += w * v.x;
            acc[4 * j + 1] += w * v.y;
            acc[4 * j + 2] += w * v.z;
            acc[4 * j + 3] += w * v.w;
        }
    }

    float* outp = g_values + ((size_t)b * DH_ + k) * T_;
#pragma unroll
    for (int t = 0; t < T_; t++) outp[t] = acc[t];
}

// ---------------- kernel 2: scores + softmax + context, ILP=4 pixels/thread ----------------
// grid = (N/(256*ILP), B), block = 256. Each thread: 4 adjacent pixels.
__global__ __launch_bounds__(256)
void attn_kernel(const float* __restrict__ img,
                 const int* __restrict__ mask,
                 float* __restrict__ out_attn,
                 float* __restrict__ out_coef) {
    __shared__ ulonglong2 svals[DH_ * T_ / 4];  // values[b] as pairs of f32x2
    __shared__ int smask[T_];

    const int b = blockIdx.y;
    const int tid = threadIdx.x;
    const int n0 = (blockIdx.x * 256 + tid) * ILP;

    const ulonglong2* gv =
        reinterpret_cast<const ulonglong2*>(g_values + (size_t)b * DH_ * T_);
    for (int i = tid; i < DH_ * T_ / 4; i += 256) svals[i] = gv[i];
    if (tid < T_) smask[tid] = mask[b * T_ + tid];
    __syncthreads();

    // ---- phase 1: S[px][t] = sum_k q[px][k] * vals[k][t] ----
    // acc[px][j] holds packed f32x2 of S; later reused for packed coefficients.
    unsigned long long acc[ILP][T_ / 2];
#pragma unroll
    for (int px = 0; px < ILP; px++)
#pragma unroll
        for (int j = 0; j < T_ / 2; j++) acc[px][j] = 0ULL;

    const float4* qb =
        reinterpret_cast<const float4*>(img + (size_t)b * DH_ * N_ + n0);
    for (int k = 0; k < DH_; k++) {
        const float4 q = qb[(size_t)k * (N_ / 4)];
        const unsigned long long q0 = pk2(q.x, q.x);
        const unsigned long long q1 = pk2(q.y, q.y);
        const unsigned long long q2 = pk2(q.z, q.z);
        const unsigned long long q3 = pk2(q.w, q.w);
        const ulonglong2* vr = &svals[k * (T_ / 4)];
#pragma unroll
        for (int j = 0; j < T_ / 4; j++) {
            const ulonglong2 v = vr[j];
            acc[0][2 * j + 0] = ffma2(q0, v.x, acc[0][2 * j + 0]);
            acc[0][2 * j + 1] = ffma2(q0, v.y, acc[0][2 * j + 1]);
            acc[1][2 * j + 0] = ffma2(q1, v.x, acc[1][2 * j + 0]);
            acc[1][2 * j + 1] = ffma2(q1, v.y, acc[1][2 * j + 1]);
            acc[2][2 * j + 0] = ffma2(q2, v.x, acc[2][2 * j + 0]);
            acc[2][2 * j + 1] = ffma2(q2, v.y, acc[2][2 * j + 1]);
            acc[3][2 * j + 0] = ffma2(q3, v.x, acc[3][2 * j + 0]);
            acc[3][2 * j + 1] = ffma2(q3, v.y, acc[3][2 * j + 1]);
        }
    }

    // ---- phase 2: masked softmax per pixel; repack p into acc in place ----
#pragma unroll
    for (int px = 0; px < ILP; px++) {
        float Sv[T_];
#pragma unroll
        for (int j = 0; j < T_ / 2; j++) {
            float2 f = unpk2(acc[px][j]);
            Sv[2 * j + 0] = f.x;
            Sv[2 * j + 1] = f.y;
        }
        float m = -CUDART_INF_F;
#pragma unroll
        for (int t = 0; t < T_; t++) {
            if (smask[t] != 0) Sv[t] = -CUDART_INF_F;
            m = fmaxf(m, Sv[t]);
        }
        float sum = 0.f;
#pragma unroll
        for (int t = 0; t < T_; t++) {
            Sv[t] = __expf(Sv[t] - m);
            sum += Sv[t];
        }
        const float inv = 1.0f / sum;
#pragma unroll
        for (int t = 0; t < T_; t++) Sv[t] *= inv;

        // write coefficients: 32 contiguous floats for pixel n0+px
        float4* oc = reinterpret_cast<float4*>(
            out_coef + ((size_t)b * N_ + n0 + px) * T_);
#pragma unroll
        for (int j = 0; j < T_ / 4; j++) {
            float4 v;
            v.x = Sv[4 * j + 0];
            v.y = Sv[4 * j + 1];
            v.z = Sv[4 * j + 2];
            v.w = Sv[4 * j + 3];
            oc[j] = v;
        }
        // repack normalized p into acc[px] for phase 3
#pragma unroll
        for (int j = 0; j < T_ / 2; j++)
            acc[px][j] = pk2(Sv[2 * j], Sv[2 * j + 1]);
    }

    // ---- phase 3: attn[px][k] = sum_t vals[k][t] * p[px][t] ----
    float4* oa =
        reinterpret_cast<float4*>(out_attn + (size_t)b * DH_ * N_ + n0);
    for (int k = 0; k < DH_; k++) {
        const ulonglong2* vr = &svals[k * (T_ / 4)];
        unsigned long long a0A = 0ULL, a0B = 0ULL;
        unsigned long long a1A = 0ULL, a1B = 0ULL;
        unsigned long long a2A = 0ULL, a2B = 0ULL;
        unsigned long long a3A = 0ULL, a3B = 0ULL;
#pragma unroll
        for (int j = 0; j < T_ / 4; j++) {
            const ulonglong2 v = vr[j];
            a0A = ffma2(v.x, acc[0][2 * j + 0], a0A);
            a0B = ffma2(v.y, acc[0][2 * j + 1], a0B);
            a1A = ffma2(v.x, acc[1][2 * j + 0], a1A);
            a1B = ffma2(v.y, acc[1][2 * j + 1], a1B);
            a2A = ffma2(v.x, acc[2][2 * j + 0], a2A);
            a2B = ffma2(v.y, acc[2][2 * j + 1], a2B);
            a3A = ffma2(v.x, acc[3][2 * j + 0], a3A);
            a3B = ffma2(v.y, acc[3][2 * j + 1], a3B);
        }
        float4 r;
        {
            float2 fA = unpk2(a0A), fB = unpk2(a0B);
            r.x = (fA.x + fB.x) + (fA.y + fB.y);
        }
        {
            float2 fA = unpk2(a1A), fB = unpk2(a1B);
            r.y = (fA.x + fB.x) + (fA.y + fB.y);
        }
        {
            float2 fA = unpk2(a2A), fB = unpk2(a2B);
            r.z = (fA.x + fB.x) + (fA.y + fB.y);
        }
        {
            float2 fA = unpk2(a3A), fB = unpk2(a3B);
            r.w = (fA.x + fB.x) + (fA.y + fB.y);
        }
        oa[(size_t)k * (N_ / 4)] = r;
    }
}

extern "C" void kernel_launch(void* const* d_in, const int* in_sizes, int n_in,
                              void* d_out, int out_size) {
    const float* wf   = (const float*)d_in[0];
    const float* img  = (const float*)d_in[1];
    const int*   msk  = (const int*)d_in[2];
    const float* Wm   = (const float*)d_in[3];
    const float* bias = (const float*)d_in[4];

    float* out_attn = (float*)d_out;
    float* out_coef = (float*)d_out + (size_t)B_ * DH_ * N_;

    values_kernel<<<B_, DH_>>>(wf, Wm, bias);

    dim3 grid(N_ / (256 * ILP), B_);
    attn_kernel<<<grid, 256>>>(img, msk, out_attn, out_coef);
}

// round 3
// speedup vs baseline: 1.3225x; 1.3225x over previous
#include <cuda_runtime.h>
#include <math_constants.h>
#include <cstdint>

// Shapes (fixed):
//   word_features  [B, D, T]   = [32, 256, 32]   fp32   d_in[0]
//   image_features [B, Dh,H,W] = [32, 128,128,128] fp32 d_in[1]
//   words_mask     [B, T]      = [32, 32]        int32  d_in[2]
//   W              [Dh, D]     = [128, 256]      fp32   d_in[3]
//   b              [Dh]        = [128]           fp32   d_in[4]
// Outputs: attn [B,Dh,N] at 0, attn_coefficients [B,N,T] at B*Dh*N.

#define B_   32
#define D_   256
#define T_   32
#define DH_  128
#define N_   16384
#define ILP  2

__device__ float g_values[B_ * DH_ * T_];

// ---------------- packed f32x2 helpers ----------------
__device__ __forceinline__ unsigned long long pk2(float lo, float hi) {
    unsigned long long r;
    asm("mov.b64 %0, {%1, %2};" : "=l"(r) : "f"(lo), "f"(hi));
    return r;
}
__device__ __forceinline__ float2 unpk2(unsigned long long v) {
    float2 f;
    asm("mov.b64 {%0, %1}, %2;" : "=f"(f.x), "=f"(f.y) : "l"(v));
    return f;
}
__device__ __forceinline__ unsigned long long ffma2(unsigned long long a,
                                                    unsigned long long b,
                                                    unsigned long long c) {
    unsigned long long d;
    asm("fma.rn.f32x2 %0, %1, %2, %3;" : "=l"(d) : "l"(a), "l"(b), "l"(c));
    return d;
}

// ---------------- kernel 1: values = W * wf + b ----------------
__global__ void values_kernel(const float* __restrict__ wf,
                              const float* __restrict__ Wm,
                              const float* __restrict__ bias) {
    __shared__ float swf[D_ * T_];
    const int b = blockIdx.x;
    const int k = threadIdx.x;

    const float* wfb = wf + (size_t)b * D_ * T_;
    for (int i = threadIdx.x; i < D_ * T_; i += blockDim.x)
        swf[i] = wfb[i];
    __syncthreads();

    float acc[T_];
    const float bk = bias[k];
#pragma unroll
    for (int t = 0; t < T_; t++) acc[t] = bk;

    const float* wrow = Wm + (size_t)k * D_;
#pragma unroll 4
    for (int d = 0; d < D_; d++) {
        const float w = wrow[d];
        const float4* row4 = reinterpret_cast<const float4*>(&swf[d * T_]);
#pragma unroll
        for (int j = 0; j < T_ / 4; j++) {
            float4 v = row4[j];
            acc[4 * j + 0] += w * v.x;
            acc[4 * j + 1] += w * v.y;
            acc[4 * j + 2] += w * v.z;
            acc[4 * j + 3] += w * v.w;
        }
    }

    float* outp = g_values + ((size_t)b * DH_ + k) * T_;
#pragma unroll
    for (int t = 0; t < T_; t++) outp[t] = acc[t];
}

// ---------------- kernel 2: scores + softmax + context ----------------
// grid = (N/(256*ILP), B), block = 256, 2 CTAs/SM. 2 adjacent pixels/thread.
__global__ __launch_bounds__(256, 2)
void attn_kernel(const float* __restrict__ img,
                 const int* __restrict__ mask,
                 float* __restrict__ out_attn,
                 float* __restrict__ out_coef) {
    __shared__ ulonglong2 svals[DH_ * T_ / 4];  // values[b]: [Dh][T] packed
    __shared__ float sneg[T_];                  // -inf where masked, else 0

    const int b = blockIdx.y;
    const int tid = threadIdx.x;
    const int n0 = (blockIdx.x * 256 + tid) * ILP;

    const ulonglong2* gv =
        reinterpret_cast<const ulonglong2*>(g_values + (size_t)b * DH_ * T_);
    for (int i = tid; i < DH_ * T_ / 4; i += 256) svals[i] = gv[i];
    if (tid < T_)
        sneg[tid] = (mask[b * T_ + tid] != 0) ? -CUDART_INF_F : 0.0f;
    __syncthreads();

    // ---- phase 1: S[px][t] = sum_k q[px][k] * vals[k][t] ----
    unsigned long long acc[ILP][T_ / 2];
#pragma unroll
    for (int px = 0; px < ILP; px++)
#pragma unroll
        for (int j = 0; j < T_ / 2; j++) acc[px][j] = 0ULL;

    const float2* qb =
        reinterpret_cast<const float2*>(img + (size_t)b * DH_ * N_ + n0);

    // prefetch 4 k-steps of q (MLP=4)
    float2 qv[4];
#pragma unroll
    for (int kk = 0; kk < 4; kk++) qv[kk] = qb[(size_t)kk * (N_ / 2)];

    for (int k = 0; k < DH_; k += 4) {
        float2 qn[4];
        if (k + 4 < DH_) {
#pragma unroll
            for (int kk = 0; kk < 4; kk++)
                qn[kk] = qb[(size_t)(k + 4 + kk) * (N_ / 2)];
        }
#pragma unroll
        for (int kk = 0; kk < 4; kk++) {
            const unsigned long long q0 = pk2(qv[kk].x, qv[kk].x);
            const unsigned long long q1 = pk2(qv[kk].y, qv[kk].y);
            const ulonglong2* vr = &svals[(k + kk) * (T_ / 4)];
#pragma unroll
            for (int j = 0; j < T_ / 4; j++) {
                const ulonglong2 v = vr[j];
                acc[0][2 * j + 0] = ffma2(q0, v.x, acc[0][2 * j + 0]);
                acc[0][2 * j + 1] = ffma2(q0, v.y, acc[0][2 * j + 1]);
                acc[1][2 * j + 0] = ffma2(q1, v.x, acc[1][2 * j + 0]);
                acc[1][2 * j + 1] = ffma2(q1, v.y, acc[1][2 * j + 1]);
            }
        }
#pragma unroll
        for (int kk = 0; kk < 4; kk++) qv[kk] = qn[kk];
    }

    // ---- phase 2: masked softmax per pixel; repack p into acc in place ----
#pragma unroll
    for (int px = 0; px < ILP; px++) {
        float Sv[T_];
#pragma unroll
        for (int j = 0; j < T_ / 2; j++) {
            float2 f = unpk2(acc[px][j]);
            Sv[2 * j + 0] = f.x;
            Sv[2 * j + 1] = f.y;
        }
        float m = -CUDART_INF_F;
#pragma unroll
        for (int t = 0; t < T_; t++) {
            Sv[t] += sneg[t];
            m = fmaxf(m, Sv[t]);
        }
        float sum = 0.f;
#pragma unroll
        for (int t = 0; t < T_; t++) {
            Sv[t] = __expf(Sv[t] - m);
            sum += Sv[t];
        }
        const float inv = 1.0f / sum;
#pragma unroll
        for (int t = 0; t < T_; t++) Sv[t] *= inv;

        float4* oc = reinterpret_cast<float4*>(
            out_coef + ((size_t)b * N_ + n0 + px) * T_);
#pragma unroll
        for (int j = 0; j < T_ / 4; j++) {
            float4 v;
            v.x = Sv[4 * j + 0];
            v.y = Sv[4 * j + 1];
            v.z = Sv[4 * j + 2];
            v.w = Sv[4 * j + 3];
            oc[j] = v;
        }
#pragma unroll
        for (int j = 0; j < T_ / 2; j++)
            acc[px][j] = pk2(Sv[2 * j], Sv[2 * j + 1]);
    }

    // ---- phase 3: attn[px][k] = sum_t vals[k][t] * p[px][t] ----
    float2* oa =
        reinterpret_cast<float2*>(out_attn + (size_t)b * DH_ * N_ + n0);
#pragma unroll 2
    for (int k = 0; k < DH_; k++) {
        const ulonglong2* vr = &svals[k * (T_ / 4)];
        unsigned long long a0A = 0ULL, a0B = 0ULL;
        unsigned long long a1A = 0ULL, a1B = 0ULL;
#pragma unroll
        for (int j = 0; j < T_ / 4; j++) {
            const ulonglong2 v = vr[j];
            a0A = ffma2(v.x, acc[0][2 * j + 0], a0A);
            a0B = ffma2(v.y, acc[0][2 * j + 1], a0B);
            a1A = ffma2(v.x, acc[1][2 * j + 0], a1A);
            a1B = ffma2(v.y, acc[1][2 * j + 1], a1B);
        }
        float2 r;
        {
            float2 fA = unpk2(a0A), fB = unpk2(a0B);
            r.x = (fA.x + fB.x) + (fA.y + fB.y);
        }
        {
            float2 fA = unpk2(a1A), fB = unpk2(a1B);
            r.y = (fA.x + fB.x) + (fA.y + fB.y);
        }
        oa[(size_t)k * (N_ / 2)] = r;
    }
}

extern "C" void kernel_launch(void* const* d_in, const int* in_sizes, int n_in,
                              void* d_out, int out_size) {
    const float* wf   = (const float*)d_in[0];
    const float* img  = (const float*)d_in[1];
    const int*   msk  = (const int*)d_in[2];
    const float* Wm   = (const float*)d_in[3];
    const float* bias = (const float*)d_in[4];

    float* out_attn = (float*)d_out;
    float* out_coef = (float*)d_out + (size_t)B_ * DH_ * N_;

    values_kernel<<<B_, DH_>>>(wf, Wm, bias);

    dim3 grid(N_ / (256 * ILP), B_);
    attn_kernel<<<grid, 256>>>(img, msk, out_attn, out_coef);
}